// round 3
// baseline (speedup 1.0000x reference)
#include <cuda_runtime.h>

#define N_NODES 100000
#define N_EDGES 3200000
#define IN_CH   512
#define HIDDEN  64
#define LOC_OUT 16
#define OUT_CH  40

// ---------------- scratch (static device globals; no runtime alloc) ----------
__device__ __align__(16) float d_deg [N_NODES];            // degree, then dinv
__device__ __align__(16) float d_g1  [N_NODES * HIDDEN];   // dinv * (X @ W1)
__device__ __align__(16) float d_acc1[N_NODES * HIDDEN];   // edge accum, then x1
__device__ __align__(16) float d_g2  [N_NODES * LOC_OUT];  // dinv * (x1 @ W2)
__device__ __align__(16) float d_acc2[N_NODES * LOC_OUT];  // edge accum layer 2
__device__ int d_idx_nonzero_odd;   // >0  =>  edge_index is int32

// ---------------- edge index fetch: handles int64 or int32 buffers -----------
__device__ __forceinline__ int load_edge(const void* ei, unsigned int pos) {
    // pos in [0, 2*N_EDGES): flat index into the logical int array
    if (d_idx_nonzero_odd == 0) {          // int64 payload (high words all 0)
        return (int)((const long long*)ei)[pos];
    } else {                               // int32 payload
        return ((const int*)ei)[pos];
    }
}

// ---------------- dtype detection: sample odd int32 slots --------------------
__global__ void k_detect(const int* __restrict__ ei32) {
    int t = threadIdx.x;                   // 256 threads, 8 samples each
    int nz = 0;
    #pragma unroll
    for (int j = 0; j < 8; j++) {
        nz |= ei32[2 * (t * 8 + j) + 1];   // odd slots of first 2048 pairs
    }
    if (nz) atomicOr(&d_idx_nonzero_odd, 1);
}

// ---------------- init: zero accumulators, deg = 1 (self loop), flag = 0 -----
__global__ void k_init() {
    int i = blockIdx.x * blockDim.x + threadIdx.x;
    float4 z = make_float4(0.f, 0.f, 0.f, 0.f);
    if (i < N_NODES * 16) ((float4*)d_acc1)[i] = z;
    if (i < N_NODES * 4)  ((float4*)d_acc2)[i] = z;
    if (i < N_NODES)      d_deg[i] = 1.0f;
    if (i == 0)           d_idx_nonzero_odd = 0;
}

// ---------------- degree count over targets (col = edge_index[1]) ------------
__global__ void k_count(const void* __restrict__ ei) {
    unsigned int e = blockIdx.x * blockDim.x + threadIdx.x;
    if (e < N_EDGES) {
        int c = load_edge(ei, N_EDGES + e);
        if ((unsigned)c < N_NODES) atomicAdd(&d_deg[c], 1.0f);
    }
}

__global__ void k_rsqrt() {
    int i = blockIdx.x * blockDim.x + threadIdx.x;
    if (i < N_NODES) d_deg[i] = rsqrtf(d_deg[i]);   // deg >= 1 always
}

// ---------------- GEMM1: g1 = dinv * (X @ W1),  [100000 x 64] ----------------
#define BM 64
#define BK 32
__global__ __launch_bounds__(256) void k_gemm1(const float* __restrict__ X,
                                               const float* __restrict__ W1) {
    __shared__ float Xs[BM][BK + 1];     // [64][33], padded
    __shared__ float Ws[BK][HIDDEN];     // [32][64]
    int tid = threadIdx.x;
    int tx = tid & 15, ty = tid >> 4;
    int row0 = blockIdx.x * BM;
    float acc[4][4] = {};

    for (int k0 = 0; k0 < IN_CH; k0 += BK) {
        #pragma unroll
        for (int i = tid; i < BM * BK; i += 256) {
            int m = i >> 5, k = i & 31;
            Xs[m][k] = (row0 + m < N_NODES)
                     ? X[(size_t)(row0 + m) * IN_CH + k0 + k] : 0.f;
        }
        #pragma unroll
        for (int i = tid; i < BK * HIDDEN; i += 256) {
            int k = i >> 6, n = i & 63;
            Ws[k][n] = W1[(size_t)(k0 + k) * HIDDEN + n];
        }
        __syncthreads();
        #pragma unroll
        for (int k = 0; k < BK; k++) {
            float4 b = *(const float4*)&Ws[k][tx * 4];
            float a0 = Xs[ty * 4 + 0][k];
            float a1 = Xs[ty * 4 + 1][k];
            float a2 = Xs[ty * 4 + 2][k];
            float a3 = Xs[ty * 4 + 3][k];
            acc[0][0] += a0 * b.x; acc[0][1] += a0 * b.y; acc[0][2] += a0 * b.z; acc[0][3] += a0 * b.w;
            acc[1][0] += a1 * b.x; acc[1][1] += a1 * b.y; acc[1][2] += a1 * b.z; acc[1][3] += a1 * b.w;
            acc[2][0] += a2 * b.x; acc[2][1] += a2 * b.y; acc[2][2] += a2 * b.z; acc[2][3] += a2 * b.w;
            acc[3][0] += a3 * b.x; acc[3][1] += a3 * b.y; acc[3][2] += a3 * b.z; acc[3][3] += a3 * b.w;
        }
        __syncthreads();
    }
    #pragma unroll
    for (int ii = 0; ii < 4; ii++) {
        int m = row0 + ty * 4 + ii;
        if (m < N_NODES) {
            float di = d_deg[m];
            float4 v = make_float4(di * acc[ii][0], di * acc[ii][1],
                                   di * acc[ii][2], di * acc[ii][3]);
            *(float4*)&d_g1[(size_t)m * HIDDEN + tx * 4] = v;
        }
    }
}

// ---------------- edge scatter (layer 1): 16 threads/edge, red.v4.f32 --------
__global__ void k_scatter1(const void* __restrict__ ei) {
    unsigned int g = blockIdx.x * blockDim.x + threadIdx.x;
    unsigned int e = g >> 4;
    if (e >= N_EDGES) return;
    int s = (g & 15) * 4;
    int r = load_edge(ei, e);
    int c = load_edge(ei, N_EDGES + e);
    if ((unsigned)r >= N_NODES || (unsigned)c >= N_NODES) return;
    float4 v = *(const float4*)&d_g1[r * HIDDEN + s];
    float* dst = &d_acc1[c * HIDDEN + s];
    asm volatile("red.global.add.v4.f32 [%0], {%1,%2,%3,%4};"
                 :: "l"(dst), "f"(v.x), "f"(v.y), "f"(v.z), "f"(v.w)
                 : "memory");
}

// ---------------- x1 = relu(dinv*(acc1+g1) + b1), in place in acc1 -----------
__global__ void k_combine1(const float* __restrict__ b1) {
    int i = blockIdx.x * blockDim.x + threadIdx.x;   // over N*16 float4s
    if (i >= N_NODES * 16) return;
    int node = i >> 4;
    int j4 = (i & 15) * 4;
    float di = d_deg[node];
    float4 a = ((const float4*)d_acc1)[i];
    float4 g = ((const float4*)d_g1)[i];
    float4 r;
    r.x = fmaxf(di * (a.x + g.x) + b1[j4 + 0], 0.f);
    r.y = fmaxf(di * (a.y + g.y) + b1[j4 + 1], 0.f);
    r.z = fmaxf(di * (a.z + g.z) + b1[j4 + 2], 0.f);
    r.w = fmaxf(di * (a.w + g.w) + b1[j4 + 3], 0.f);
    ((float4*)d_acc1)[i] = r;
}

// ---------------- GEMM2: g2 = dinv * (x1 @ W2), [100000 x 16] ----------------
__global__ __launch_bounds__(256) void k_gemm2(const float* __restrict__ W2) {
    __shared__ float Ws[HIDDEN * LOC_OUT];
    int tid = threadIdx.x;
    for (int i = tid; i < HIDDEN * LOC_OUT; i += 256) Ws[i] = W2[i];
    __syncthreads();
    int g = blockIdx.x * 256 + tid;
    if (g >= N_NODES * LOC_OUT) return;
    int node = g >> 4, col = g & 15;
    const float4* xr = (const float4*)&d_acc1[node * HIDDEN];
    float acc = 0.f;
    #pragma unroll
    for (int k4 = 0; k4 < 16; k4++) {
        float4 x = xr[k4];
        acc += x.x * Ws[(k4 * 4 + 0) * 16 + col];
        acc += x.y * Ws[(k4 * 4 + 1) * 16 + col];
        acc += x.z * Ws[(k4 * 4 + 2) * 16 + col];
        acc += x.w * Ws[(k4 * 4 + 3) * 16 + col];
    }
    d_g2[g] = d_deg[node] * acc;
}

// ---------------- edge scatter (layer 2): 4 threads/edge ---------------------
__global__ void k_scatter2(const void* __restrict__ ei) {
    unsigned int g = blockIdx.x * blockDim.x + threadIdx.x;
    unsigned int e = g >> 2;
    if (e >= N_EDGES) return;
    int s = (g & 3) * 4;
    int r = load_edge(ei, e);
    int c = load_edge(ei, N_EDGES + e);
    if ((unsigned)r >= N_NODES || (unsigned)c >= N_NODES) return;
    float4 v = *(const float4*)&d_g2[r * LOC_OUT + s];
    float* dst = &d_acc2[c * LOC_OUT + s];
    asm volatile("red.global.add.v4.f32 [%0], {%1,%2,%3,%4};"
                 :: "l"(dst), "f"(v.x), "f"(v.y), "f"(v.z), "f"(v.w)
                 : "memory");
}

// ---------------- final: x2, attention pool, linear head ---------------------
__global__ __launch_bounds__(256) void k_final(const float* __restrict__ glob,
                                               const float* __restrict__ b2,
                                               const float* __restrict__ aw1,
                                               const float* __restrict__ ab1,
                                               const float* __restrict__ aw2,
                                               const float* __restrict__ lw,
                                               const float* __restrict__ lb,
                                               float* __restrict__ out) {
    __shared__ float s_aw1[256], s_ab1[16], s_aw2[16], s_b2[16];
    __shared__ float s_lw[LOC_OUT * OUT_CH], s_lb[OUT_CH];
    int tid = threadIdx.x;
    if (tid < 256) s_aw1[tid] = aw1[tid];
    if (tid < 16) { s_ab1[tid] = ab1[tid]; s_aw2[tid] = aw2[tid]; s_b2[tid] = b2[tid]; }
    for (int i = tid; i < LOC_OUT * OUT_CH; i += 256) s_lw[i] = lw[i];
    if (tid < OUT_CH) s_lb[tid] = lb[tid];
    __syncthreads();

    int n = blockIdx.x * 256 + tid;
    if (n >= N_NODES) return;
    float di = d_deg[n];
    float z0[16], z1[16];
    const float4* a2 = (const float4*)&d_acc2[n * LOC_OUT];
    const float4* g2 = (const float4*)&d_g2[n * LOC_OUT];
    const float4* gl = (const float4*)&glob[n * LOC_OUT];
    #pragma unroll
    for (int q = 0; q < 4; q++) {
        float4 a = a2[q], g = g2[q], e = gl[q];
        z0[q*4+0] = di * (a.x + g.x) + s_b2[q*4+0];
        z0[q*4+1] = di * (a.y + g.y) + s_b2[q*4+1];
        z0[q*4+2] = di * (a.z + g.z) + s_b2[q*4+2];
        z0[q*4+3] = di * (a.w + g.w) + s_b2[q*4+3];
        z1[q*4+0] = e.x; z1[q*4+1] = e.y; z1[q*4+2] = e.z; z1[q*4+3] = e.w;
    }
    float w0 = 0.f, w1 = 0.f;
    #pragma unroll
    for (int j = 0; j < 16; j++) {
        float s0 = s_ab1[j], s1 = s_ab1[j];
        #pragma unroll
        for (int i2 = 0; i2 < 16; i2++) {
            s0 += z0[i2] * s_aw1[i2 * 16 + j];
            s1 += z1[i2] * s_aw1[i2 * 16 + j];
        }
        w0 += tanhf(s0) * s_aw2[j];
        w1 += tanhf(s1) * s_aw2[j];
    }
    float beta0 = 1.f / (1.f + expf(w1 - w0));   // softmax over 2 slots
    float beta1 = 1.f - beta0;
    float emb[16];
    #pragma unroll
    for (int i2 = 0; i2 < 16; i2++) emb[i2] = beta0 * z0[i2] + beta1 * z1[i2];
    #pragma unroll
    for (int j = 0; j < OUT_CH; j++) {
        float o = s_lb[j];
        #pragma unroll
        for (int i2 = 0; i2 < 16; i2++) o += emb[i2] * s_lw[i2 * OUT_CH + j];
        out[(size_t)n * OUT_CH + j] = o;
    }
}

// ---------------- launch ------------------------------------------------------
extern "C" void kernel_launch(void* const* d_in, const int* in_sizes, int n_in,
                              void* d_out, int out_size) {
    const float* X    = (const float*)d_in[0];
    const void*  ei   = d_in[1];
    const float* glob = (const float*)d_in[2];
    const float* W1   = (const float*)d_in[3];
    const float* b1   = (const float*)d_in[4];
    const float* W2   = (const float*)d_in[5];
    const float* b2   = (const float*)d_in[6];
    const float* aw1  = (const float*)d_in[7];
    const float* ab1  = (const float*)d_in[8];
    const float* aw2  = (const float*)d_in[9];
    const float* lw   = (const float*)d_in[10];
    const float* lb   = (const float*)d_in[11];
    float* out = (float*)d_out;

    k_init  <<<(N_NODES * 16 + 255) / 256, 256>>>();
    k_detect<<<1, 256>>>((const int*)ei);
    k_count <<<(N_EDGES + 255) / 256, 256>>>(ei);
    k_rsqrt <<<(N_NODES + 255) / 256, 256>>>();
    k_gemm1 <<<(N_NODES + BM - 1) / BM, 256>>>(X, W1);
    k_scatter1<<<(unsigned)((N_EDGES * 16u + 255u) / 256u), 256>>>(ei);
    k_combine1<<<(N_NODES * 16 + 255) / 256, 256>>>(b1);
    k_gemm2 <<<(N_NODES * 16 + 255) / 256, 256>>>(W2);
    k_scatter2<<<(unsigned)((N_EDGES * 4u + 255u) / 256u), 256>>>(ei);
    k_final <<<(N_NODES + 255) / 256, 256>>>(glob, b2, aw1, ab1, aw2, lw, lb, out);
}

// round 5
// speedup vs baseline: 1.0462x; 1.0462x over previous
#include <cuda_runtime.h>

#define N_NODES 100000
#define N_EDGES 3200000
#define IN_CH   512
#define HIDDEN  64
#define LOC_OUT 16
#define OUT_CH  40

// ---------------- scratch (static device globals; no runtime alloc) ----------
__device__ __align__(16) float d_deg [N_NODES];            // degree, then dinv
__device__ __align__(16) float d_g1  [N_NODES * HIDDEN];   // dinv * (X @ W1)
__device__ __align__(16) float d_acc1[N_NODES * HIDDEN];   // edge accum layer 1
__device__ __align__(16) float d_g2  [N_NODES * LOC_OUT];  // dinv * (x1 @ W2)
__device__ __align__(16) float d_acc2[N_NODES * LOC_OUT];  // edge accum layer 2
__device__ int d_idx_nonzero_odd;   // >0  =>  edge_index is int32

// ---------------- packed f32x2 helpers ---------------------------------------
__device__ __forceinline__ unsigned long long dup2(float a) {
    unsigned long long r;
    asm("mov.b64 %0, {%1, %1};" : "=l"(r) : "f"(a));
    return r;
}
__device__ __forceinline__ unsigned long long pack2(float lo, float hi) {
    unsigned long long r;
    asm("mov.b64 %0, {%1, %2};" : "=l"(r) : "f"(lo), "f"(hi));
    return r;
}
__device__ __forceinline__ void fma2(unsigned long long& d,
                                     unsigned long long a, unsigned long long b) {
    asm("fma.rn.f32x2 %0, %1, %2, %0;" : "+l"(d) : "l"(a), "l"(b));
}
__device__ __forceinline__ void unpack2(unsigned long long v, float& lo, float& hi) {
    asm("mov.b64 {%0, %1}, %2;" : "=f"(lo), "=f"(hi) : "l"(v));
}

// ---------------- edge index fetch: handles int64 or int32 buffers -----------
__device__ __forceinline__ int load_edge(const void* ei, unsigned int pos) {
    if (d_idx_nonzero_odd == 0) {          // int64 payload (high words all 0)
        return (int)((const long long*)ei)[pos];
    } else {                               // int32 payload
        return ((const int*)ei)[pos];
    }
}

// ---------------- dtype detection: sample odd int32 slots --------------------
__global__ void k_detect(const int* __restrict__ ei32) {
    int t = threadIdx.x;                   // 256 threads, 8 samples each
    int nz = 0;
    #pragma unroll
    for (int j = 0; j < 8; j++) {
        nz |= ei32[2 * (t * 8 + j) + 1];
    }
    if (nz) atomicOr(&d_idx_nonzero_odd, 1);
}

// ---------------- init: zero accumulators, deg = 1 (self loop), flag = 0 -----
__global__ void k_init() {
    int i = blockIdx.x * blockDim.x + threadIdx.x;
    float4 z = make_float4(0.f, 0.f, 0.f, 0.f);
    if (i < N_NODES * 16) ((float4*)d_acc1)[i] = z;
    if (i < N_NODES * 4)  ((float4*)d_acc2)[i] = z;
    if (i < N_NODES)      d_deg[i] = 1.0f;
    if (i == 0)           d_idx_nonzero_odd = 0;
}

// ---------------- degree count over targets (col = edge_index[1]) ------------
__global__ void k_count(const void* __restrict__ ei) {
    unsigned int e = blockIdx.x * blockDim.x + threadIdx.x;
    if (e < N_EDGES) {
        int c = load_edge(ei, N_EDGES + e);
        if ((unsigned)c < N_NODES) atomicAdd(&d_deg[c], 1.0f);
    }
}

__global__ void k_rsqrt() {
    int i = blockIdx.x * blockDim.x + threadIdx.x;
    if (i < N_NODES) d_deg[i] = rsqrtf(d_deg[i]);   // deg >= 1 always
}

// ---------------- GEMM1: g1 = dinv * (X @ W1),  [100000 x 64] ----------------
// BM=256 rows x BN=64 cols per block, 256 threads, 8x8 per thread, FFMA2.
#define BM 256
#define BK 32
#define XS_STRIDE (BM + 4)      // 260: keeps LDS.128 16B-aligned, spreads banks

__global__ __launch_bounds__(256, 1) void k_gemm1(const float* __restrict__ X,
                                                  const float* __restrict__ W1) {
    __shared__ float Xs[BK * XS_STRIDE];   // k-major: Xs[k*260 + m]
    __shared__ float Ws[BK * HIDDEN];      // k-major: Ws[k*64 + n]
    int tid = threadIdx.x;
    int tx = tid & 7;          // col group: cols tx*8 .. tx*8+7
    int ty = tid >> 3;         // row group: rows ty*8 .. ty*8+7 (0..31)
    int row0 = blockIdx.x * BM;

    unsigned long long acc[8][4];
    #pragma unroll
    for (int i = 0; i < 8; i++)
        #pragma unroll
        for (int j = 0; j < 4; j++) acc[i][j] = 0ULL;   // two packed +0.0f

    for (int k0 = 0; k0 < IN_CH; k0 += BK) {
        // --- load X tile (256 x 32) into k-major smem -------------------------
        #pragma unroll
        for (int it = 0; it < 8; it++) {
            int m  = (tid >> 3) + it * 32;     // 0..255
            int kq = (tid & 7) * 4;            // 0,4,...,28
            int gr = row0 + m;
            float4 v = (gr < N_NODES)
                     ? *(const float4*)&X[(size_t)gr * IN_CH + k0 + kq]
                     : make_float4(0.f, 0.f, 0.f, 0.f);
            Xs[(kq + 0) * XS_STRIDE + m] = v.x;
            Xs[(kq + 1) * XS_STRIDE + m] = v.y;
            Xs[(kq + 2) * XS_STRIDE + m] = v.z;
            Xs[(kq + 3) * XS_STRIDE + m] = v.w;
        }
        // --- load W tile (32 x 64), contiguous copy ---------------------------
        #pragma unroll
        for (int it = 0; it < 2; it++) {
            int f4 = tid + it * 256;           // 0..511 float4s
            ((float4*)Ws)[f4] = ((const float4*)&W1[(size_t)k0 * HIDDEN])[f4];
        }
        __syncthreads();

        #pragma unroll
        for (int k = 0; k < BK; k++) {
            const float* xr = &Xs[k * XS_STRIDE + ty * 8];
            float4 a0 = *(const float4*)xr;
            float4 a1 = *(const float4*)(xr + 4);
            const ulonglong2* bw = (const ulonglong2*)&Ws[k * HIDDEN + tx * 8];
            ulonglong2 bA = bw[0];             // cols tx*8+0..3 (2 pairs)
            ulonglong2 bB = bw[1];             // cols tx*8+4..7
            unsigned long long A[8];
            A[0] = dup2(a0.x); A[1] = dup2(a0.y); A[2] = dup2(a0.z); A[3] = dup2(a0.w);
            A[4] = dup2(a1.x); A[5] = dup2(a1.y); A[6] = dup2(a1.z); A[7] = dup2(a1.w);
            #pragma unroll
            for (int i = 0; i < 8; i++) {
                fma2(acc[i][0], A[i], bA.x);
                fma2(acc[i][1], A[i], bA.y);
                fma2(acc[i][2], A[i], bB.x);
                fma2(acc[i][3], A[i], bB.y);
            }
        }
        __syncthreads();
    }

    // --- epilogue: scale by dinv, store 2 float4 per row ---------------------
    #pragma unroll
    for (int i = 0; i < 8; i++) {
        int r = row0 + ty * 8 + i;
        if (r < N_NODES) {
            float di = d_deg[r];
            float o[8];
            #pragma unroll
            for (int j = 0; j < 4; j++) unpack2(acc[i][j], o[2 * j], o[2 * j + 1]);
            float4 v0 = make_float4(di * o[0], di * o[1], di * o[2], di * o[3]);
            float4 v1 = make_float4(di * o[4], di * o[5], di * o[6], di * o[7]);
            float* dst = &d_g1[(size_t)r * HIDDEN + tx * 8];
            *(float4*)dst       = v0;
            *(float4*)(dst + 4) = v1;
        }
    }
}

// ---------------- edge scatter (layer 1): 16 threads/edge, red.v4.f32 --------
__global__ void k_scatter1(const void* __restrict__ ei) {
    unsigned int g = blockIdx.x * blockDim.x + threadIdx.x;
    unsigned int e = g >> 4;
    if (e >= N_EDGES) return;
    int s = (g & 15) * 4;
    int r = load_edge(ei, e);
    int c = load_edge(ei, N_EDGES + e);
    if ((unsigned)r >= N_NODES || (unsigned)c >= N_NODES) return;
    float4 v = *(const float4*)&d_g1[r * HIDDEN + s];
    float* dst = &d_acc1[c * HIDDEN + s];
    asm volatile("red.global.add.v4.f32 [%0], {%1,%2,%3,%4};"
                 :: "l"(dst), "f"(v.x), "f"(v.y), "f"(v.z), "f"(v.w)
                 : "memory");
}

// ---------------- fused: x1 = relu(dinv*(acc1+g1)+b1); g2 = dinv*(x1 @ W2) ---
__global__ __launch_bounds__(256) void k_mid(const float* __restrict__ b1,
                                             const float* __restrict__ W2) {
    __shared__ float W2T[LOC_OUT][HIDDEN];   // W2T[j][k] = W2[k*16 + j]
    __shared__ float s_b1[HIDDEN];
    int tid = threadIdx.x;
    if (tid < HIDDEN) s_b1[tid] = b1[tid];
    for (int i = tid; i < HIDDEN * LOC_OUT; i += 256) {
        int k = i >> 4, j = i & 15;
        W2T[j][k] = W2[i];
    }
    __syncthreads();

    int n = blockIdx.x * 256 + tid;
    if (n >= N_NODES) return;
    float di = d_deg[n];

    unsigned long long xp[32];               // x1 as 32 packed f32x2 pairs
    const float4* aa = (const float4*)&d_acc1[(size_t)n * HIDDEN];
    const float4* gg = (const float4*)&d_g1[(size_t)n * HIDDEN];
    #pragma unroll
    for (int q = 0; q < 16; q++) {
        float4 a = aa[q], g = gg[q];
        float x0 = fmaxf(di * (a.x + g.x) + s_b1[q * 4 + 0], 0.f);
        float x1 = fmaxf(di * (a.y + g.y) + s_b1[q * 4 + 1], 0.f);
        float x2 = fmaxf(di * (a.z + g.z) + s_b1[q * 4 + 2], 0.f);
        float x3 = fmaxf(di * (a.w + g.w) + s_b1[q * 4 + 3], 0.f);
        xp[2 * q]     = pack2(x0, x1);
        xp[2 * q + 1] = pack2(x2, x3);
    }

    float o[LOC_OUT];
    #pragma unroll
    for (int j = 0; j < LOC_OUT; j++) {
        unsigned long long acc0 = 0ULL, acc1v = 0ULL;
        const ulonglong2* w = (const ulonglong2*)&W2T[j][0];
        #pragma unroll
        for (int q = 0; q < 16; q++) {       // 16 x ulonglong2 = 64 floats of W2T row
            ulonglong2 wv = w[q];
            fma2(acc0,  xp[2 * q],     wv.x);
            fma2(acc1v, xp[2 * q + 1], wv.y);
        }
        float l0, h0, l1, h1;
        unpack2(acc0, l0, h0);
        unpack2(acc1v, l1, h1);
        o[j] = di * ((l0 + h0) + (l1 + h1));
    }
    float4* dst = (float4*)&d_g2[(size_t)n * LOC_OUT];
    dst[0] = make_float4(o[0],  o[1],  o[2],  o[3]);
    dst[1] = make_float4(o[4],  o[5],  o[6],  o[7]);
    dst[2] = make_float4(o[8],  o[9],  o[10], o[11]);
    dst[3] = make_float4(o[12], o[13], o[14], o[15]);
}

// ---------------- edge scatter (layer 2): 4 threads/edge ---------------------
__global__ void k_scatter2(const void* __restrict__ ei) {
    unsigned int g = blockIdx.x * blockDim.x + threadIdx.x;
    unsigned int e = g >> 2;
    if (e >= N_EDGES) return;
    int s = (g & 3) * 4;
    int r = load_edge(ei, e);
    int c = load_edge(ei, N_EDGES + e);
    if ((unsigned)r >= N_NODES || (unsigned)c >= N_NODES) return;
    float4 v = *(const float4*)&d_g2[r * LOC_OUT + s];
    float* dst = &d_acc2[c * LOC_OUT + s];
    asm volatile("red.global.add.v4.f32 [%0], {%1,%2,%3,%4};"
                 :: "l"(dst), "f"(v.x), "f"(v.y), "f"(v.z), "f"(v.w)
                 : "memory");
}

// ---------------- final: x2, attention pool, linear head ---------------------
__global__ __launch_bounds__(256) void k_final(const float* __restrict__ glob,
                                               const float* __restrict__ b2,
                                               const float* __restrict__ aw1,
                                               const float* __restrict__ ab1,
                                               const float* __restrict__ aw2,
                                               const float* __restrict__ lw,
                                               const float* __restrict__ lb,
                                               float* __restrict__ out) {
    __shared__ float s_aw1[256], s_ab1[16], s_aw2[16], s_b2[16];
    __shared__ float s_lw[LOC_OUT * OUT_CH], s_lb[OUT_CH];
    int tid = threadIdx.x;
    if (tid < 256) s_aw1[tid] = aw1[tid];
    if (tid < 16) { s_ab1[tid] = ab1[tid]; s_aw2[tid] = aw2[tid]; s_b2[tid] = b2[tid]; }
    for (int i = tid; i < LOC_OUT * OUT_CH; i += 256) s_lw[i] = lw[i];
    if (tid < OUT_CH) s_lb[tid] = lb[tid];
    __syncthreads();

    int n = blockIdx.x * 256 + tid;
    if (n >= N_NODES) return;
    float di = d_deg[n];
    float z0[16], z1[16];
    const float4* a2 = (const float4*)&d_acc2[n * LOC_OUT];
    const float4* g2 = (const float4*)&d_g2[n * LOC_OUT];
    const float4* gl = (const float4*)&glob[n * LOC_OUT];
    #pragma unroll
    for (int q = 0; q < 4; q++) {
        float4 a = a2[q], g = g2[q], e = gl[q];
        z0[q*4+0] = di * (a.x + g.x) + s_b2[q*4+0];
        z0[q*4+1] = di * (a.y + g.y) + s_b2[q*4+1];
        z0[q*4+2] = di * (a.z + g.z) + s_b2[q*4+2];
        z0[q*4+3] = di * (a.w + g.w) + s_b2[q*4+3];
        z1[q*4+0] = e.x; z1[q*4+1] = e.y; z1[q*4+2] = e.z; z1[q*4+3] = e.w;
    }
    float w0 = 0.f, w1 = 0.f;
    #pragma unroll
    for (int j = 0; j < 16; j++) {
        float s0 = s_ab1[j], s1 = s_ab1[j];
        #pragma unroll
        for (int i2 = 0; i2 < 16; i2++) {
            s0 += z0[i2] * s_aw1[i2 * 16 + j];
            s1 += z1[i2] * s_aw1[i2 * 16 + j];
        }
        w0 += tanhf(s0) * s_aw2[j];
        w1 += tanhf(s1) * s_aw2[j];
    }
    float beta0 = 1.f / (1.f + expf(w1 - w0));   // softmax over 2 slots
    float beta1 = 1.f - beta0;
    float emb[16];
    #pragma unroll
    for (int i2 = 0; i2 < 16; i2++) emb[i2] = beta0 * z0[i2] + beta1 * z1[i2];
    #pragma unroll
    for (int j = 0; j < OUT_CH; j++) {
        float o = s_lb[j];
        #pragma unroll
        for (int i2 = 0; i2 < 16; i2++) o += emb[i2] * s_lw[i2 * OUT_CH + j];
        out[(size_t)n * OUT_CH + j] = o;
    }
}

// ---------------- launch ------------------------------------------------------
extern "C" void kernel_launch(void* const* d_in, const int* in_sizes, int n_in,
                              void* d_out, int out_size) {
    const float* X    = (const float*)d_in[0];
    const void*  ei   = d_in[1];
    const float* glob = (const float*)d_in[2];
    const float* W1   = (const float*)d_in[3];
    const float* b1   = (const float*)d_in[4];
    const float* W2   = (const float*)d_in[5];
    const float* b2   = (const float*)d_in[6];
    const float* aw1  = (const float*)d_in[7];
    const float* ab1  = (const float*)d_in[8];
    const float* aw2  = (const float*)d_in[9];
    const float* lw   = (const float*)d_in[10];
    const float* lb   = (const float*)d_in[11];
    float* out = (float*)d_out;

    k_init  <<<(N_NODES * 16 + 255) / 256, 256>>>();
    k_detect<<<1, 256>>>((const int*)ei);
    k_count <<<(N_EDGES + 255) / 256, 256>>>(ei);
    k_rsqrt <<<(N_NODES + 255) / 256, 256>>>();
    k_gemm1 <<<(N_NODES + BM - 1) / BM, 256>>>(X, W1);
    k_scatter1<<<(unsigned)((N_EDGES * 16u + 255u) / 256u), 256>>>(ei);
    k_mid   <<<(N_NODES + 255) / 256, 256>>>(b1, W2);
    k_scatter2<<<(unsigned)((N_EDGES * 4u + 255u) / 256u), 256>>>(ei);
    k_final <<<(N_NODES + 255) / 256, 256>>>(glob, b2, aw1, ab1, aw2, lw, lb, out);
}